// round 14
// baseline (speedup 1.0000x reference)
#include <cuda_runtime.h>
#include <cuda_bf16.h>
#include <math.h>

// Problem: B=2, S=2048, D=1024, N_COMPRESS=64, RANK=64, TOP_K=2
#define TOKENS 4096
#define DIM    1024
#define NEXP   64
#define RANK   64
#define CAP    8192
#define NSPLIT 4          // proj D-splits (256 d each)
#define DSPL   256
#define TILE_P 128        // picks per proj tile (MMA M)

#define OFF_IDX (TOKENS * RANK)
#define OFF_W   (TOKENS * RANK + TOKENS*2)

typedef unsigned long long ull;
typedef unsigned int u32;
typedef unsigned short u16;

__device__ __forceinline__ ull fma2(ull a, ull b, ull c) {
    ull d; asm("fma.rn.f32x2 %0, %1, %2, %3;" : "=l"(d) : "l"(a), "l"(b), "l"(c)); return d;
}
__device__ __forceinline__ float2 unpack2(ull v) {
    float2 r; asm("mov.b64 {%0, %1}, %2;" : "=f"(r.x), "=f"(r.y) : "l"(v)); return r;
}
// m16n8k16 bf16 MMA, fp32 accum (base-target instruction, sm_80+)
__device__ __forceinline__ void mma16816(float* c, const u32* a, u32 b0, u32 b1) {
    asm volatile(
        "mma.sync.aligned.m16n8k16.row.col.f32.bf16.bf16.f32 "
        "{%0,%1,%2,%3}, {%4,%5,%6,%7}, {%8,%9}, {%0,%1,%2,%3};"
        : "+f"(c[0]), "+f"(c[1]), "+f"(c[2]), "+f"(c[3])
        : "r"(a[0]), "r"(a[1]), "r"(a[2]), "r"(a[3]), "r"(b0), "r"(b1));
}
__device__ __forceinline__ u32 pack_bf2(__nv_bfloat16 lo, __nv_bfloat16 hi) {
    return ((u32)__bfloat16_as_ushort(hi) << 16) | __bfloat16_as_ushort(lo);
}

// ---- scratch (device globals) ----
__device__ int   g_cnt[NEXP];
__device__ int   g_list[NEXP * CAP];
__device__ float g_w[TOKENS * 2];
__device__ float g_part[2 * TOKENS * NEXP];             // router partials (2 D-splits)
__device__ float g_scratch[NSPLIT * TOKENS * 2 * RANK]; // proj partials
// pre-converted bf16 hi/lo operands
__device__ __nv_bfloat16 g_xh[TOKENS * DIM];
__device__ __nv_bfloat16 g_xl[TOKENS * DIM];
__device__ __nv_bfloat16 g_nh[NEXP * DIM * RANK];
__device__ __nv_bfloat16 g_nl[NEXP * DIM * RANK];

// ============================================================
// Kernel 0: neurons fp32 -> bf16 hi/lo (streaming, coalesced)
// ============================================================
__global__ __launch_bounds__(256) void k_nconv(const float* __restrict__ neurons) {
    int i = (blockIdx.x * 256 + threadIdx.x) * 4;
    float4 v = *(const float4*)(neurons + i);
    __nv_bfloat16 hx = __float2bfloat16_rn(v.x);
    __nv_bfloat16 hy = __float2bfloat16_rn(v.y);
    __nv_bfloat16 hz = __float2bfloat16_rn(v.z);
    __nv_bfloat16 hw = __float2bfloat16_rn(v.w);
    __nv_bfloat16 lx = __float2bfloat16_rn(v.x - __bfloat162float(hx));
    __nv_bfloat16 ly = __float2bfloat16_rn(v.y - __bfloat162float(hy));
    __nv_bfloat16 lz = __float2bfloat16_rn(v.z - __bfloat162float(hz));
    __nv_bfloat16 lw = __float2bfloat16_rn(v.w - __bfloat162float(hw));
    *(uint2*)(g_nh + i) = make_uint2(pack_bf2(hx, hy), pack_bf2(hz, hw));
    *(uint2*)(g_nl + i) = make_uint2(pack_bf2(lx, ly), pack_bf2(lz, lw));
}

// ============================================================
// Kernel 1: router partials (R8-proven) + fused x -> bf16 hi/lo
// (each x element is read exactly once across the (64,2) grid).
// ============================================================
__global__ __launch_bounds__(256) void k_router(
    const float* __restrict__ x, const float* __restrict__ W)
{
    __shared__ __align__(16) float xs[64][36];
    __shared__ __align__(16) float ws[64][34];

    const int tid = threadIdx.x;
    if (blockIdx.x == 0 && blockIdx.y == 0 && tid < NEXP) g_cnt[tid] = 0;

    const int ty  = tid >> 4;
    const int tx  = tid & 15;
    const int tok0 = blockIdx.x * 64;
    const int d0   = blockIdx.y * 512;

    ull acc[4][4];
    #pragma unroll
    for (int i = 0; i < 4; i++)
        #pragma unroll
        for (int j = 0; j < 4; j++) acc[i][j] = 0ull;

    for (int dc = 0; dc < 512; dc += 32) {
        #pragma unroll
        for (int r = 0; r < 2; r++) {
            int idx = tid + r * 256;
            int t = idx >> 3, c = idx & 7;
            size_t xoff = (size_t)(tok0 + t) * DIM + d0 + dc + 4 * c;
            float4 v = *(const float4*)(x + xoff);
            *(float4*)&xs[t][4*c] = v;
            // fused conversion: x -> bf16 hi/lo
            {
                __nv_bfloat16 hx = __float2bfloat16_rn(v.x);
                __nv_bfloat16 hy = __float2bfloat16_rn(v.y);
                __nv_bfloat16 hz = __float2bfloat16_rn(v.z);
                __nv_bfloat16 hw = __float2bfloat16_rn(v.w);
                __nv_bfloat16 lx = __float2bfloat16_rn(v.x - __bfloat162float(hx));
                __nv_bfloat16 ly = __float2bfloat16_rn(v.y - __bfloat162float(hy));
                __nv_bfloat16 lz = __float2bfloat16_rn(v.z - __bfloat162float(hz));
                __nv_bfloat16 lw = __float2bfloat16_rn(v.w - __bfloat162float(hw));
                *(uint2*)(g_xh + xoff) = make_uint2(pack_bf2(hx, hy), pack_bf2(hz, hw));
                *(uint2*)(g_xl + xoff) = make_uint2(pack_bf2(lx, ly), pack_bf2(lz, lw));
            }
            float4 u = *(const float4*)(W + (size_t)t * DIM + d0 + dc + 4 * c);
            ws[t][4*c+0] = u.x; ws[t][4*c+1] = u.y; ws[t][4*c+2] = u.z; ws[t][4*c+3] = u.w;
        }
        __syncthreads();

        #pragma unroll
        for (int k = 0; k < 32; k += 4) {
            ulonglong2 a[4];
            #pragma unroll
            for (int i = 0; i < 4; i++)
                a[i] = *(const ulonglong2*)&xs[ty + 16*i][k];
            #pragma unroll
            for (int h = 0; h < 2; h++) {
                ull b[4];
                #pragma unroll
                for (int j = 0; j < 4; j++) b[j] = *(const ull*)&ws[tx + 16*j][k + 2*h];
                #pragma unroll
                for (int i = 0; i < 4; i++) {
                    ull av = h ? a[i].y : a[i].x;
                    #pragma unroll
                    for (int j = 0; j < 4; j++)
                        acc[i][j] = fma2(av, b[j], acc[i][j]);
                }
            }
        }
        __syncthreads();
    }

    float* dst = g_part + (size_t)blockIdx.y * TOKENS * NEXP + (size_t)tok0 * NEXP;
    #pragma unroll
    for (int i = 0; i < 4; i++)
        #pragma unroll
        for (int j = 0; j < 4; j++) {
            float2 p = unpack2(acc[i][j]);
            dst[(ty + 16*i) * NEXP + tx + 16*j] = p.x + p.y;
        }
}

// ============================================================
// Kernel 2: combine 2 partials, top-2, softmax, outputs, scatter.
// ============================================================
__global__ __launch_bounds__(128) void k_top2(float* __restrict__ out, int out_size) {
    int t = blockIdx.x * blockDim.x + threadIdx.x;
    const float4* p0 = (const float4*)(g_part) + (size_t)t * 16;
    const float4* p1 = (const float4*)(g_part + (size_t)TOKENS * NEXP) + (size_t)t * 16;

    float m0 = -1e30f, m1 = -1e30f; int i0 = 0, i1 = 0;
    #pragma unroll
    for (int c = 0; c < 16; c++) {
        float4 a = p0[c], b = p1[c];
        float s[4] = { a.x + b.x, a.y + b.y, a.z + b.z, a.w + b.w };
        #pragma unroll
        for (int e = 0; e < 4; e++) {
            int n = 4*c + e;
            float v = s[e];
            if (v > m0)      { m1 = m0; i1 = i0; m0 = v; i0 = n; }
            else if (v > m1) { m1 = v; i1 = n; }
        }
    }
    float w0 = 1.0f / (1.0f + __expf(m1 - m0));
    float w1 = 1.0f - w0;

    g_w[t*2 + 0] = w0;
    g_w[t*2 + 1] = w1;
    if (out_size >= OFF_IDX + TOKENS*2) {
        out[OFF_IDX + t*2 + 0] = (float)i0;
        out[OFF_IDX + t*2 + 1] = (float)i1;
    }
    if (out_size >= OFF_W + TOKENS*2) {
        out[OFF_W + t*2 + 0] = w0;
        out[OFF_W + t*2 + 1] = w1;
    }
    int p = atomicAdd(&g_cnt[i0], 1);
    g_list[i0 * CAP + p] = t*2 + 0;
    p = atomicAdd(&g_cnt[i1], 1);
    g_list[i1 * CAP + p] = t*2 + 1;
}

// ============================================================
// Kernel 3: tensor-core projection via mma.sync (R13-proven MMA core).
// Operands now pre-converted bf16 hi/lo -> loop is copies + HMMA only.
// Per tile: M=128 picks x N=64 rank x K=256 (split-K x4).
// D = hh + hl + lh. Raw fp32 partials to disjoint scratch -> k_reduce.
// ============================================================
__global__ __launch_bounds__(256) void k_proj_mma(
    const float* __restrict__ x, const float* __restrict__ neurons)
{
    __shared__ __align__(16) __nv_bfloat16 Ah[TILE_P][40];
    __shared__ __align__(16) __nv_bfloat16 Al[TILE_P][40];
    __shared__ __align__(16) __nv_bfloat16 Bh[RANK][40];
    __shared__ __align__(16) __nv_bfloat16 Bl[RANK][40];
    __shared__ int psh[TILE_P];
    __shared__ int tsh[TILE_P];
    __shared__ int s_nt[NEXP];
    __shared__ int s_base[NEXP + 1];

    const int tid = threadIdx.x;
    const int wid = tid >> 5;
    const int lid = tid & 31;
    const int g   = lid >> 2;        // 0..7
    const int t2  = (lid & 3) * 2;   // 0,2,4,6
    const int strip = wid * 16;

    if (tid < NEXP) s_nt[tid] = (g_cnt[tid] + TILE_P - 1) >> 7;
    __syncthreads();
    if (tid == 0) {
        int sum = 0;
        #pragma unroll
        for (int e = 0; e < NEXP; e++) { s_base[e] = sum; sum += s_nt[e]; }
        s_base[NEXP] = sum;
    }
    __syncthreads();
    const int nwork = s_base[NEXP] * NSPLIT;

    for (int w = blockIdx.x; w < nwork; w += gridDim.x) {
        const int it = w >> 2;
        const int sp = w & 3;
        int e = 0;
        while (s_base[e + 1] <= it) e++;
        const int off = (it - s_base[e]) * TILE_P;
        int cnt = g_cnt[e] - off;
        if (cnt > TILE_P) cnt = TILE_P;

        if (tid < TILE_P) {
            if (tid < cnt) {
                int p = g_list[e * CAP + off + tid];
                psh[tid] = p;
                tsh[tid] = p >> 1;
            } else {
                psh[tid] = -1;
                tsh[tid] = -1;
            }
        }
        __syncthreads();

        float C[8][4];
        #pragma unroll
        for (int j = 0; j < 8; j++)
            #pragma unroll
            for (int q = 0; q < 4; q++) C[j][q] = 0.0f;

        const size_t nboff = (size_t)e * DIM * RANK + (size_t)sp * DSPL * RANK;
        const int dbase = sp * DSPL;

        for (int dc = 0; dc < DSPL; dc += 32) {
            // A: 128 picks x 32 d bf16 hi/lo — gathered uint4 copies
            #pragma unroll
            for (int s = 0; s < 2; s++) {
                int idx = tid + 256 * s;            // 0..511
                int pr = idx >> 2, c = idx & 3;     // pick row, 16B unit (8 bf16)
                int tok = tsh[pr];
                uint4 h4 = make_uint4(0u, 0u, 0u, 0u);
                uint4 l4 = make_uint4(0u, 0u, 0u, 0u);
                if (tok >= 0) {
                    size_t xo = (size_t)tok * DIM + dbase + dc + 8 * c;
                    h4 = *(const uint4*)(g_xh + xo);
                    l4 = *(const uint4*)(g_xl + xo);
                }
                *(uint4*)&Ah[pr][8*c] = h4;
                *(uint4*)&Al[pr][8*c] = l4;
            }
            // B: 32 d x 64 r bf16 hi/lo -> transposed [r][k] (plain moves)
            #pragma unroll
            for (int s = 0; s < 2; s++) {
                int idx = tid + 256 * s;            // 0..511
                int d = idx >> 4, rc = idx & 15;
                size_t no = nboff + (size_t)(dc + d) * RANK + 4 * rc;
                uint2 h2 = *(const uint2*)(g_nh + no);
                uint2 l2 = *(const uint2*)(g_nl + no);
                Bh[4*rc+0][d] = __ushort_as_bfloat16((u16)(h2.x & 0xffff));
                Bh[4*rc+1][d] = __ushort_as_bfloat16((u16)(h2.x >> 16));
                Bh[4*rc+2][d] = __ushort_as_bfloat16((u16)(h2.y & 0xffff));
                Bh[4*rc+3][d] = __ushort_as_bfloat16((u16)(h2.y >> 16));
                Bl[4*rc+0][d] = __ushort_as_bfloat16((u16)(l2.x & 0xffff));
                Bl[4*rc+1][d] = __ushort_as_bfloat16((u16)(l2.x >> 16));
                Bl[4*rc+2][d] = __ushort_as_bfloat16((u16)(l2.y & 0xffff));
                Bl[4*rc+3][d] = __ushort_as_bfloat16((u16)(l2.y >> 16));
            }
            __syncthreads();

            #pragma unroll
            for (int koff = 0; koff < 32; koff += 16) {
                u32 ah[4], al[4];
                ah[0] = *(const u32*)&Ah[strip + g    ][koff + t2];
                ah[1] = *(const u32*)&Ah[strip + g + 8][koff + t2];
                ah[2] = *(const u32*)&Ah[strip + g    ][koff + t2 + 8];
                ah[3] = *(const u32*)&Ah[strip + g + 8][koff + t2 + 8];
                al[0] = *(const u32*)&Al[strip + g    ][koff + t2];
                al[1] = *(const u32*)&Al[strip + g + 8][koff + t2];
                al[2] = *(const u32*)&Al[strip + g    ][koff + t2 + 8];
                al[3] = *(const u32*)&Al[strip + g + 8][koff + t2 + 8];
                #pragma unroll
                for (int j = 0; j < 8; j++) {
                    u32 bh0 = *(const u32*)&Bh[8*j + g][koff + t2];
                    u32 bh1 = *(const u32*)&Bh[8*j + g][koff + t2 + 8];
                    u32 bl0 = *(const u32*)&Bl[8*j + g][koff + t2];
                    u32 bl1 = *(const u32*)&Bl[8*j + g][koff + t2 + 8];
                    mma16816(C[j], ah, bh0, bh1);   // hh
                    mma16816(C[j], ah, bl0, bl1);   // hl
                    mma16816(C[j], al, bh0, bh1);   // lh
                }
            }
            __syncthreads();
        }

        // epilogue: C frag -> disjoint (split, pick) scratch rows
        float* sb = g_scratch + (size_t)sp * (TOKENS * 2) * RANK;
        int p0 = psh[strip + g];
        int p1 = psh[strip + g + 8];
        #pragma unroll
        for (int j = 0; j < 8; j++) {
            if (p0 >= 0)
                *(float2*)(sb + (size_t)p0 * RANK + 8*j + t2) = make_float2(C[j][0], C[j][1]);
            if (p1 >= 0)
                *(float2*)(sb + (size_t)p1 * RANK + 8*j + t2) = make_float2(C[j][2], C[j][3]);
        }
        __syncthreads();
    }
}

// ============================================================
// Kernel 4: deterministic reduce: out[t,r] = sum_k w_k * sum_s part
// ============================================================
__global__ __launch_bounds__(256) void k_reduce(float* __restrict__ out) {
    int i = blockIdx.x * blockDim.x + threadIdx.x;
    int t = i >> 4;
    int c = (i & 15) * 4;
    float4 acc = make_float4(0.f, 0.f, 0.f, 0.f);
    #pragma unroll
    for (int k = 0; k < 2; k++) {
        int p = t*2 + k;
        float w = g_w[p];
        #pragma unroll
        for (int s = 0; s < NSPLIT; s++) {
            float4 v = *(const float4*)&g_scratch[((size_t)s * (TOKENS*2) + p) * RANK + c];
            acc.x += w * v.x; acc.y += w * v.y; acc.z += w * v.z; acc.w += w * v.w;
        }
    }
    *(float4*)&out[(size_t)t * RANK + c] = acc;
}

// ============================================================
extern "C" void kernel_launch(void* const* d_in, const int* in_sizes, int n_in,
                              void* d_out, int out_size) {
    const float* x       = (const float*)d_in[0];
    const float* router  = (const float*)d_in[1];
    const float* neurons = (const float*)d_in[2];
    float* out = (float*)d_out;

    k_nconv<<<NEXP * DIM * RANK / 4 / 256, 256>>>(neurons);
    k_router<<<dim3(TOKENS/64, 2), 256>>>(x, router);
    k_top2<<<TOKENS/128, 128>>>(out, out_size);
    k_proj_mma<<<296, 256>>>(x, neurons);
    k_reduce<<<TOKENS*RANK/4/256, 256>>>(out);
}

// round 15
// speedup vs baseline: 1.1546x; 1.1546x over previous
#include <cuda_runtime.h>
#include <cuda_bf16.h>
#include <math.h>

// Problem: B=2, S=2048, D=1024, N_COMPRESS=64, RANK=64, TOP_K=2
#define TOKENS 4096
#define DIM    1024
#define NEXP   64
#define RANK   64
#define CAP    8192
#define NSPLIT 4          // proj D-splits (256 d each)
#define DSPL   256
#define TILE_P 128        // picks per proj tile (MMA M)

#define OFF_IDX (TOKENS * RANK)
#define OFF_W   (TOKENS * RANK + TOKENS*2)

typedef unsigned long long ull;
typedef unsigned int u32;
typedef unsigned short u16;

__device__ __forceinline__ ull fma2(ull a, ull b, ull c) {
    ull d; asm("fma.rn.f32x2 %0, %1, %2, %3;" : "=l"(d) : "l"(a), "l"(b), "l"(c)); return d;
}
__device__ __forceinline__ float2 unpack2(ull v) {
    float2 r; asm("mov.b64 {%0, %1}, %2;" : "=f"(r.x), "=f"(r.y) : "l"(v)); return r;
}
__device__ __forceinline__ void mma16816(float* c, const u32* a, u32 b0, u32 b1) {
    asm volatile(
        "mma.sync.aligned.m16n8k16.row.col.f32.bf16.bf16.f32 "
        "{%0,%1,%2,%3}, {%4,%5,%6,%7}, {%8,%9}, {%0,%1,%2,%3};"
        : "+f"(c[0]), "+f"(c[1]), "+f"(c[2]), "+f"(c[3])
        : "r"(a[0]), "r"(a[1]), "r"(a[2]), "r"(a[3]), "r"(b0), "r"(b1));
}
__device__ __forceinline__ void ldsm_x4(u32& r0, u32& r1, u32& r2, u32& r3, u32 addr) {
    asm volatile("ldmatrix.sync.aligned.m8n8.x4.shared.b16 {%0,%1,%2,%3}, [%4];"
        : "=r"(r0), "=r"(r1), "=r"(r2), "=r"(r3) : "r"(addr));
}
__device__ __forceinline__ void ldsm_x4_t(u32& r0, u32& r1, u32& r2, u32& r3, u32 addr) {
    asm volatile("ldmatrix.sync.aligned.m8n8.x4.trans.shared.b16 {%0,%1,%2,%3}, [%4];"
        : "=r"(r0), "=r"(r1), "=r"(r2), "=r"(r3) : "r"(addr));
}
__device__ __forceinline__ u32 smem_u32(const void* p) {
    u32 a;
    asm("{ .reg .u64 t; cvta.to.shared.u64 t, %1; cvt.u32.u64 %0, t; }" : "=r"(a) : "l"(p));
    return a;
}
__device__ __forceinline__ u32 pack_bf2(__nv_bfloat16 lo, __nv_bfloat16 hi) {
    return ((u32)__bfloat16_as_ushort(hi) << 16) | __bfloat16_as_ushort(lo);
}

// ---- scratch (device globals) ----
__device__ int   g_cnt[NEXP];
__device__ int   g_list[NEXP * CAP];
__device__ float g_w[TOKENS * 2];
__device__ float g_part[2 * TOKENS * NEXP];
__device__ float g_scratch[NSPLIT * TOKENS * 2 * RANK];
__device__ __nv_bfloat16 g_xh[TOKENS * DIM];
__device__ __nv_bfloat16 g_xl[TOKENS * DIM];
__device__ __nv_bfloat16 g_nh[NEXP * DIM * RANK];
__device__ __nv_bfloat16 g_nl[NEXP * DIM * RANK];

// ============================================================
// Kernel 0: neurons fp32 -> bf16 hi/lo (streaming, coalesced)
// ============================================================
__global__ __launch_bounds__(256) void k_nconv(const float* __restrict__ neurons) {
    int i = (blockIdx.x * 256 + threadIdx.x) * 4;
    float4 v = *(const float4*)(neurons + i);
    __nv_bfloat16 hx = __float2bfloat16_rn(v.x);
    __nv_bfloat16 hy = __float2bfloat16_rn(v.y);
    __nv_bfloat16 hz = __float2bfloat16_rn(v.z);
    __nv_bfloat16 hw = __float2bfloat16_rn(v.w);
    __nv_bfloat16 lx = __float2bfloat16_rn(v.x - __bfloat162float(hx));
    __nv_bfloat16 ly = __float2bfloat16_rn(v.y - __bfloat162float(hy));
    __nv_bfloat16 lz = __float2bfloat16_rn(v.z - __bfloat162float(hz));
    __nv_bfloat16 lw = __float2bfloat16_rn(v.w - __bfloat162float(hw));
    *(uint2*)(g_nh + i) = make_uint2(pack_bf2(hx, hy), pack_bf2(hz, hw));
    *(uint2*)(g_nl + i) = make_uint2(pack_bf2(lx, ly), pack_bf2(lz, lw));
}

// ============================================================
// Kernel 1: router partials (R8-proven) + fused x -> bf16 hi/lo.
// ============================================================
__global__ __launch_bounds__(256) void k_router(
    const float* __restrict__ x, const float* __restrict__ W)
{
    __shared__ __align__(16) float xs[64][36];
    __shared__ __align__(16) float ws[64][34];

    const int tid = threadIdx.x;
    if (blockIdx.x == 0 && blockIdx.y == 0 && tid < NEXP) g_cnt[tid] = 0;

    const int ty  = tid >> 4;
    const int tx  = tid & 15;
    const int tok0 = blockIdx.x * 64;
    const int d0   = blockIdx.y * 512;

    ull acc[4][4];
    #pragma unroll
    for (int i = 0; i < 4; i++)
        #pragma unroll
        for (int j = 0; j < 4; j++) acc[i][j] = 0ull;

    for (int dc = 0; dc < 512; dc += 32) {
        #pragma unroll
        for (int r = 0; r < 2; r++) {
            int idx = tid + r * 256;
            int t = idx >> 3, c = idx & 7;
            size_t xoff = (size_t)(tok0 + t) * DIM + d0 + dc + 4 * c;
            float4 v = *(const float4*)(x + xoff);
            *(float4*)&xs[t][4*c] = v;
            {
                __nv_bfloat16 hx = __float2bfloat16_rn(v.x);
                __nv_bfloat16 hy = __float2bfloat16_rn(v.y);
                __nv_bfloat16 hz = __float2bfloat16_rn(v.z);
                __nv_bfloat16 hw = __float2bfloat16_rn(v.w);
                __nv_bfloat16 lx = __float2bfloat16_rn(v.x - __bfloat162float(hx));
                __nv_bfloat16 ly = __float2bfloat16_rn(v.y - __bfloat162float(hy));
                __nv_bfloat16 lz = __float2bfloat16_rn(v.z - __bfloat162float(hz));
                __nv_bfloat16 lw = __float2bfloat16_rn(v.w - __bfloat162float(hw));
                *(uint2*)(g_xh + xoff) = make_uint2(pack_bf2(hx, hy), pack_bf2(hz, hw));
                *(uint2*)(g_xl + xoff) = make_uint2(pack_bf2(lx, ly), pack_bf2(lz, lw));
            }
            float4 u = *(const float4*)(W + (size_t)t * DIM + d0 + dc + 4 * c);
            ws[t][4*c+0] = u.x; ws[t][4*c+1] = u.y; ws[t][4*c+2] = u.z; ws[t][4*c+3] = u.w;
        }
        __syncthreads();

        #pragma unroll
        for (int k = 0; k < 32; k += 4) {
            ulonglong2 a[4];
            #pragma unroll
            for (int i = 0; i < 4; i++)
                a[i] = *(const ulonglong2*)&xs[ty + 16*i][k];
            #pragma unroll
            for (int h = 0; h < 2; h++) {
                ull b[4];
                #pragma unroll
                for (int j = 0; j < 4; j++) b[j] = *(const ull*)&ws[tx + 16*j][k + 2*h];
                #pragma unroll
                for (int i = 0; i < 4; i++) {
                    ull av = h ? a[i].y : a[i].x;
                    #pragma unroll
                    for (int j = 0; j < 4; j++)
                        acc[i][j] = fma2(av, b[j], acc[i][j]);
                }
            }
        }
        __syncthreads();
    }

    float* dst = g_part + (size_t)blockIdx.y * TOKENS * NEXP + (size_t)tok0 * NEXP;
    #pragma unroll
    for (int i = 0; i < 4; i++)
        #pragma unroll
        for (int j = 0; j < 4; j++) {
            float2 p = unpack2(acc[i][j]);
            dst[(ty + 16*i) * NEXP + tx + 16*j] = p.x + p.y;
        }
}

// ============================================================
// Kernel 2: combine 2 partials, top-2, softmax, outputs, scatter.
// ============================================================
__global__ __launch_bounds__(128) void k_top2(float* __restrict__ out, int out_size) {
    int t = blockIdx.x * blockDim.x + threadIdx.x;
    const float4* p0 = (const float4*)(g_part) + (size_t)t * 16;
    const float4* p1 = (const float4*)(g_part + (size_t)TOKENS * NEXP) + (size_t)t * 16;

    float m0 = -1e30f, m1 = -1e30f; int i0 = 0, i1 = 0;
    #pragma unroll
    for (int c = 0; c < 16; c++) {
        float4 a = p0[c], b = p1[c];
        float s[4] = { a.x + b.x, a.y + b.y, a.z + b.z, a.w + b.w };
        #pragma unroll
        for (int e = 0; e < 4; e++) {
            int n = 4*c + e;
            float v = s[e];
            if (v > m0)      { m1 = m0; i1 = i0; m0 = v; i0 = n; }
            else if (v > m1) { m1 = v; i1 = n; }
        }
    }
    float w0 = 1.0f / (1.0f + __expf(m1 - m0));
    float w1 = 1.0f - w0;

    g_w[t*2 + 0] = w0;
    g_w[t*2 + 1] = w1;
    if (out_size >= OFF_IDX + TOKENS*2) {
        out[OFF_IDX + t*2 + 0] = (float)i0;
        out[OFF_IDX + t*2 + 1] = (float)i1;
    }
    if (out_size >= OFF_W + TOKENS*2) {
        out[OFF_W + t*2 + 0] = w0;
        out[OFF_W + t*2 + 1] = w1;
    }
    int p = atomicAdd(&g_cnt[i0], 1);
    g_list[i0 * CAP + p] = t*2 + 0;
    p = atomicAdd(&g_cnt[i1], 1);
    g_list[i1 * CAP + p] = t*2 + 1;
}

// ============================================================
// Kernel 3: tensor-core projection. M=128 x N=64 x K=256, split-K x4.
// A: [m][k] SMEM (stride 40, 5x16B -> ldmatrix conflict-free),
//    frags via ldmatrix.x4.
// B: [k][n] SMEM (stride 72, 9x16B -> ldmatrix conflict-free),
//    staged as plain uint4 copies, frags via ldmatrix.x4.trans
//    (transposed fragment of [k][n] tile == mma B operand).
// D = hh + hl + lh. Raw partials -> disjoint scratch -> k_reduce.
// ============================================================
__global__ __launch_bounds__(256, 2) void k_proj_mma(
    const float* __restrict__ x, const float* __restrict__ neurons)
{
    __shared__ __align__(16) __nv_bfloat16 Ah[TILE_P][40];
    __shared__ __align__(16) __nv_bfloat16 Al[TILE_P][40];
    __shared__ __align__(16) __nv_bfloat16 Bh[32][72];
    __shared__ __align__(16) __nv_bfloat16 Bl[32][72];
    __shared__ int psh[TILE_P];
    __shared__ int tsh[TILE_P];
    __shared__ int s_nt[NEXP];
    __shared__ int s_base[NEXP + 1];

    const int tid = threadIdx.x;
    const int wid = tid >> 5;
    const int lid = tid & 31;
    const int g   = lid >> 2;        // 0..7
    const int t2  = (lid & 3) * 2;   // 0,2,4,6
    const int strip = wid * 16;

    const u32 Ah_b = smem_u32(&Ah[0][0]);
    const u32 Al_b = smem_u32(&Al[0][0]);
    const u32 Bh_b = smem_u32(&Bh[0][0]);
    const u32 Bl_b = smem_u32(&Bl[0][0]);

    // ldmatrix lane-address components
    const int a_row = strip + (lid & 7) + ((lid >> 3) & 1) * 8;  // m row
    const int a_kh  = ((lid >> 4) & 1) * 8;                       // k half
    const int b_krow = ((lid >> 3) & 1) * 8 + (lid & 7);          // k row within chunk half
    const int b_nh   = ((lid >> 4) & 1) * 8;                      // n half within j-pair

    if (tid < NEXP) s_nt[tid] = (g_cnt[tid] + TILE_P - 1) >> 7;
    __syncthreads();
    if (tid == 0) {
        int sum = 0;
        #pragma unroll
        for (int e = 0; e < NEXP; e++) { s_base[e] = sum; sum += s_nt[e]; }
        s_base[NEXP] = sum;
    }
    __syncthreads();
    const int nwork = s_base[NEXP] * NSPLIT;

    for (int w = blockIdx.x; w < nwork; w += gridDim.x) {
        const int it = w >> 2;
        const int sp = w & 3;
        int e = 0;
        while (s_base[e + 1] <= it) e++;
        const int off = (it - s_base[e]) * TILE_P;
        int cnt = g_cnt[e] - off;
        if (cnt > TILE_P) cnt = TILE_P;

        if (tid < TILE_P) {
            if (tid < cnt) {
                int p = g_list[e * CAP + off + tid];
                psh[tid] = p;
                tsh[tid] = p >> 1;
            } else {
                psh[tid] = -1;
                tsh[tid] = -1;
            }
        }
        __syncthreads();

        float C[8][4];
        #pragma unroll
        for (int j = 0; j < 8; j++)
            #pragma unroll
            for (int q = 0; q < 4; q++) C[j][q] = 0.0f;

        const size_t nboff = (size_t)e * DIM * RANK + (size_t)sp * DSPL * RANK;
        const int dbase = sp * DSPL;

        for (int dc = 0; dc < DSPL; dc += 32) {
            // A: 128 picks x 32 d bf16 hi/lo — gathered uint4 copies
            #pragma unroll
            for (int s = 0; s < 2; s++) {
                int idx = tid + 256 * s;            // 0..511
                int pr = idx >> 2, c = idx & 3;     // pick row, 16B unit
                int tok = tsh[pr];
                uint4 h4 = make_uint4(0u, 0u, 0u, 0u);
                uint4 l4 = make_uint4(0u, 0u, 0u, 0u);
                if (tok >= 0) {
                    size_t xo = (size_t)tok * DIM + dbase + dc + 8 * c;
                    h4 = *(const uint4*)(g_xh + xo);
                    l4 = *(const uint4*)(g_xl + xo);
                }
                *(uint4*)&Ah[pr][8*c] = h4;
                *(uint4*)&Al[pr][8*c] = l4;
            }
            // B: 32 d x 64 r, natural [d][r] layout — plain uint4 copies
            {
                int d = tid >> 3, u = tid & 7;      // 32 d rows x 8 16B-units
                size_t no = nboff + (size_t)(dc + d) * RANK + 8 * u;
                *(uint4*)&Bh[d][8*u] = *(const uint4*)(g_nh + no);
                *(uint4*)&Bl[d][8*u] = *(const uint4*)(g_nl + no);
            }
            __syncthreads();

            #pragma unroll
            for (int koff = 0; koff < 32; koff += 16) {
                u32 ah[4], al[4];
                {
                    u32 ao = (u32)(a_row * 40 + koff + a_kh) * 2;
                    ldsm_x4(ah[0], ah[1], ah[2], ah[3], Ah_b + ao);
                    ldsm_x4(al[0], al[1], al[2], al[3], Al_b + ao);
                }
                #pragma unroll
                for (int q = 0; q < 4; q++) {
                    u32 bo = (u32)((koff + b_krow) * 72 + 16 * q + b_nh) * 2;
                    u32 bh0a, bh1a, bh0b, bh1b, bl0a, bl1a, bl0b, bl1b;
                    ldsm_x4_t(bh0a, bh1a, bh0b, bh1b, Bh_b + bo);
                    ldsm_x4_t(bl0a, bl1a, bl0b, bl1b, Bl_b + bo);
                    mma16816(C[2*q],   ah, bh0a, bh1a);   // hh
                    mma16816(C[2*q],   ah, bl0a, bl1a);   // hl
                    mma16816(C[2*q],   al, bh0a, bh1a);   // lh
                    mma16816(C[2*q+1], ah, bh0b, bh1b);
                    mma16816(C[2*q+1], ah, bl0b, bl1b);
                    mma16816(C[2*q+1], al, bh0b, bh1b);
                }
            }
            __syncthreads();
        }

        // epilogue: C frag -> disjoint (split, pick) scratch rows
        float* sb = g_scratch + (size_t)sp * (TOKENS * 2) * RANK;
        int p0 = psh[strip + g];
        int p1 = psh[strip + g + 8];
        #pragma unroll
        for (int j = 0; j < 8; j++) {
            if (p0 >= 0)
                *(float2*)(sb + (size_t)p0 * RANK + 8*j + t2) = make_float2(C[j][0], C[j][1]);
            if (p1 >= 0)
                *(float2*)(sb + (size_t)p1 * RANK + 8*j + t2) = make_float2(C[j][2], C[j][3]);
        }
        __syncthreads();
    }
}

// ============================================================
// Kernel 4: deterministic reduce: out[t,r] = sum_k w_k * sum_s part
// ============================================================
__global__ __launch_bounds__(256) void k_reduce(float* __restrict__ out) {
    int i = blockIdx.x * blockDim.x + threadIdx.x;
    int t = i >> 4;
    int c = (i & 15) * 4;
    float4 acc = make_float4(0.f, 0.f, 0.f, 0.f);
    #pragma unroll
    for (int k = 0; k < 2; k++) {
        int p = t*2 + k;
        float w = g_w[p];
        #pragma unroll
        for (int s = 0; s < NSPLIT; s++) {
            float4 v = *(const float4*)&g_scratch[((size_t)s * (TOKENS*2) + p) * RANK + c];
            acc.x += w * v.x; acc.y += w * v.y; acc.z += w * v.z; acc.w += w * v.w;
        }
    }
    *(float4*)&out[(size_t)t * RANK + c] = acc;
}

// ============================================================
extern "C" void kernel_launch(void* const* d_in, const int* in_sizes, int n_in,
                              void* d_out, int out_size) {
    const float* x       = (const float*)d_in[0];
    const float* router  = (const float*)d_in[1];
    const float* neurons = (const float*)d_in[2];
    float* out = (float*)d_out;

    k_nconv<<<NEXP * DIM * RANK / 4 / 256, 256>>>(neurons);
    k_router<<<dim3(TOKENS/64, 2), 256>>>(x, router);
    k_top2<<<TOKENS/128, 128>>>(out, out_size);
    k_proj_mma<<<296, 256>>>(x, neurons);
    k_reduce<<<TOKENS*RANK/4/256, 256>>>(out);
}

// round 16
// speedup vs baseline: 1.2735x; 1.1030x over previous
#include <cuda_runtime.h>
#include <cuda_bf16.h>
#include <math.h>

// Problem: B=2, S=2048, D=1024, N_COMPRESS=64, RANK=64, TOP_K=2
#define TOKENS 4096
#define DIM    1024
#define NEXP   64
#define RANK   64
#define CAP    8192
#define NSPLIT 4          // proj D-splits (256 d each)
#define DSPL   256
#define TILE_P 128        // picks per proj tile (MMA M)

#define OFF_IDX (TOKENS * RANK)
#define OFF_W   (TOKENS * RANK + TOKENS*2)

typedef unsigned long long ull;
typedef unsigned int u32;
typedef unsigned short u16;

__device__ __forceinline__ ull fma2(ull a, ull b, ull c) {
    ull d; asm("fma.rn.f32x2 %0, %1, %2, %3;" : "=l"(d) : "l"(a), "l"(b), "l"(c)); return d;
}
__device__ __forceinline__ float2 unpack2(ull v) {
    float2 r; asm("mov.b64 {%0, %1}, %2;" : "=f"(r.x), "=f"(r.y) : "l"(v)); return r;
}
__device__ __forceinline__ void mma16816(float* c, const u32* a, u32 b0, u32 b1) {
    asm volatile(
        "mma.sync.aligned.m16n8k16.row.col.f32.bf16.bf16.f32 "
        "{%0,%1,%2,%3}, {%4,%5,%6,%7}, {%8,%9}, {%0,%1,%2,%3};"
        : "+f"(c[0]), "+f"(c[1]), "+f"(c[2]), "+f"(c[3])
        : "r"(a[0]), "r"(a[1]), "r"(a[2]), "r"(a[3]), "r"(b0), "r"(b1));
}
__device__ __forceinline__ void ldsm_x4(u32& r0, u32& r1, u32& r2, u32& r3, u32 addr) {
    asm volatile("ldmatrix.sync.aligned.m8n8.x4.shared.b16 {%0,%1,%2,%3}, [%4];"
        : "=r"(r0), "=r"(r1), "=r"(r2), "=r"(r3) : "r"(addr));
}
__device__ __forceinline__ void ldsm_x4_t(u32& r0, u32& r1, u32& r2, u32& r3, u32 addr) {
    asm volatile("ldmatrix.sync.aligned.m8n8.x4.trans.shared.b16 {%0,%1,%2,%3}, [%4];"
        : "=r"(r0), "=r"(r1), "=r"(r2), "=r"(r3) : "r"(addr));
}
__device__ __forceinline__ u32 smem_u32(const void* p) {
    u32 a;
    asm("{ .reg .u64 t; cvta.to.shared.u64 t, %1; cvt.u32.u64 %0, t; }" : "=r"(a) : "l"(p));
    return a;
}
__device__ __forceinline__ u32 pack_bf2(__nv_bfloat16 lo, __nv_bfloat16 hi) {
    return ((u32)__bfloat16_as_ushort(hi) << 16) | __bfloat16_as_ushort(lo);
}
// cp.async 16B with zfill (src_size 0 -> zero fill)
__device__ __forceinline__ void cp16(u32 dst, const void* src, u32 src_size) {
    asm volatile("cp.async.cg.shared.global [%0], [%1], 16, %2;"
                 :: "r"(dst), "l"(src), "r"(src_size) : "memory");
}
__device__ __forceinline__ void cp_commit() {
    asm volatile("cp.async.commit_group;" ::: "memory");
}
template <int N>
__device__ __forceinline__ void cp_wait() {
    asm volatile("cp.async.wait_group %0;" :: "n"(N) : "memory");
}

// dynamic smem layout for k_proj_mma (bytes, per buffer)
#define PB_AH 0
#define PB_AL 10240        // Ah[128][40] bf16
#define PB_BH 20480        // Al same
#define PB_BL 25088        // Bh[32][72] bf16 = 4608
#define PB_SZ 29696        // buffer stride
#define PROJ_DYN_SMEM (2 * PB_SZ)

// ---- scratch (device globals) ----
__device__ int   g_cnt[NEXP];
__device__ int   g_list[NEXP * CAP];
__device__ float g_w[TOKENS * 2];
__device__ float g_part[2 * TOKENS * NEXP];
__device__ float g_scratch[NSPLIT * TOKENS * 2 * RANK];
__device__ __nv_bfloat16 g_xh[TOKENS * DIM];
__device__ __nv_bfloat16 g_xl[TOKENS * DIM];
__device__ __nv_bfloat16 g_nh[NEXP * DIM * RANK];
__device__ __nv_bfloat16 g_nl[NEXP * DIM * RANK];

// ============================================================
// Kernel 0: neurons fp32 -> bf16 hi/lo (streaming, coalesced)
// ============================================================
__global__ __launch_bounds__(256) void k_nconv(const float* __restrict__ neurons) {
    int i = (blockIdx.x * 256 + threadIdx.x) * 4;
    float4 v = *(const float4*)(neurons + i);
    __nv_bfloat16 hx = __float2bfloat16_rn(v.x);
    __nv_bfloat16 hy = __float2bfloat16_rn(v.y);
    __nv_bfloat16 hz = __float2bfloat16_rn(v.z);
    __nv_bfloat16 hw = __float2bfloat16_rn(v.w);
    __nv_bfloat16 lx = __float2bfloat16_rn(v.x - __bfloat162float(hx));
    __nv_bfloat16 ly = __float2bfloat16_rn(v.y - __bfloat162float(hy));
    __nv_bfloat16 lz = __float2bfloat16_rn(v.z - __bfloat162float(hz));
    __nv_bfloat16 lw = __float2bfloat16_rn(v.w - __bfloat162float(hw));
    *(uint2*)(g_nh + i) = make_uint2(pack_bf2(hx, hy), pack_bf2(hz, hw));
    *(uint2*)(g_nl + i) = make_uint2(pack_bf2(lx, ly), pack_bf2(lz, lw));
}

// ============================================================
// Kernel 1: router partials (R8-proven) + fused x -> bf16 hi/lo.
// ============================================================
__global__ __launch_bounds__(256) void k_router(
    const float* __restrict__ x, const float* __restrict__ W)
{
    __shared__ __align__(16) float xs[64][36];
    __shared__ __align__(16) float ws[64][34];

    const int tid = threadIdx.x;
    if (blockIdx.x == 0 && blockIdx.y == 0 && tid < NEXP) g_cnt[tid] = 0;

    const int ty  = tid >> 4;
    const int tx  = tid & 15;
    const int tok0 = blockIdx.x * 64;
    const int d0   = blockIdx.y * 512;

    ull acc[4][4];
    #pragma unroll
    for (int i = 0; i < 4; i++)
        #pragma unroll
        for (int j = 0; j < 4; j++) acc[i][j] = 0ull;

    for (int dc = 0; dc < 512; dc += 32) {
        #pragma unroll
        for (int r = 0; r < 2; r++) {
            int idx = tid + r * 256;
            int t = idx >> 3, c = idx & 7;
            size_t xoff = (size_t)(tok0 + t) * DIM + d0 + dc + 4 * c;
            float4 v = *(const float4*)(x + xoff);
            *(float4*)&xs[t][4*c] = v;
            {
                __nv_bfloat16 hx = __float2bfloat16_rn(v.x);
                __nv_bfloat16 hy = __float2bfloat16_rn(v.y);
                __nv_bfloat16 hz = __float2bfloat16_rn(v.z);
                __nv_bfloat16 hw = __float2bfloat16_rn(v.w);
                __nv_bfloat16 lx = __float2bfloat16_rn(v.x - __bfloat162float(hx));
                __nv_bfloat16 ly = __float2bfloat16_rn(v.y - __bfloat162float(hy));
                __nv_bfloat16 lz = __float2bfloat16_rn(v.z - __bfloat162float(hz));
                __nv_bfloat16 lw = __float2bfloat16_rn(v.w - __bfloat162float(hw));
                *(uint2*)(g_xh + xoff) = make_uint2(pack_bf2(hx, hy), pack_bf2(hz, hw));
                *(uint2*)(g_xl + xoff) = make_uint2(pack_bf2(lx, ly), pack_bf2(lz, lw));
            }
            float4 u = *(const float4*)(W + (size_t)t * DIM + d0 + dc + 4 * c);
            ws[t][4*c+0] = u.x; ws[t][4*c+1] = u.y; ws[t][4*c+2] = u.z; ws[t][4*c+3] = u.w;
        }
        __syncthreads();

        #pragma unroll
        for (int k = 0; k < 32; k += 4) {
            ulonglong2 a[4];
            #pragma unroll
            for (int i = 0; i < 4; i++)
                a[i] = *(const ulonglong2*)&xs[ty + 16*i][k];
            #pragma unroll
            for (int h = 0; h < 2; h++) {
                ull b[4];
                #pragma unroll
                for (int j = 0; j < 4; j++) b[j] = *(const ull*)&ws[tx + 16*j][k + 2*h];
                #pragma unroll
                for (int i = 0; i < 4; i++) {
                    ull av = h ? a[i].y : a[i].x;
                    #pragma unroll
                    for (int j = 0; j < 4; j++)
                        acc[i][j] = fma2(av, b[j], acc[i][j]);
                }
            }
        }
        __syncthreads();
    }

    float* dst = g_part + (size_t)blockIdx.y * TOKENS * NEXP + (size_t)tok0 * NEXP;
    #pragma unroll
    for (int i = 0; i < 4; i++)
        #pragma unroll
        for (int j = 0; j < 4; j++) {
            float2 p = unpack2(acc[i][j]);
            dst[(ty + 16*i) * NEXP + tx + 16*j] = p.x + p.y;
        }
}

// ============================================================
// Kernel 2: combine 2 partials, top-2, softmax, outputs, scatter.
// ============================================================
__global__ __launch_bounds__(128) void k_top2(float* __restrict__ out, int out_size) {
    int t = blockIdx.x * blockDim.x + threadIdx.x;
    const float4* p0 = (const float4*)(g_part) + (size_t)t * 16;
    const float4* p1 = (const float4*)(g_part + (size_t)TOKENS * NEXP) + (size_t)t * 16;

    float m0 = -1e30f, m1 = -1e30f; int i0 = 0, i1 = 0;
    #pragma unroll
    for (int c = 0; c < 16; c++) {
        float4 a = p0[c], b = p1[c];
        float s[4] = { a.x + b.x, a.y + b.y, a.z + b.z, a.w + b.w };
        #pragma unroll
        for (int e = 0; e < 4; e++) {
            int n = 4*c + e;
            float v = s[e];
            if (v > m0)      { m1 = m0; i1 = i0; m0 = v; i0 = n; }
            else if (v > m1) { m1 = v; i1 = n; }
        }
    }
    float w0 = 1.0f / (1.0f + __expf(m1 - m0));
    float w1 = 1.0f - w0;

    g_w[t*2 + 0] = w0;
    g_w[t*2 + 1] = w1;
    if (out_size >= OFF_IDX + TOKENS*2) {
        out[OFF_IDX + t*2 + 0] = (float)i0;
        out[OFF_IDX + t*2 + 1] = (float)i1;
    }
    if (out_size >= OFF_W + TOKENS*2) {
        out[OFF_W + t*2 + 0] = w0;
        out[OFF_W + t*2 + 1] = w1;
    }
    int p = atomicAdd(&g_cnt[i0], 1);
    g_list[i0 * CAP + p] = t*2 + 0;
    p = atomicAdd(&g_cnt[i1], 1);
    g_list[i1 * CAP + p] = t*2 + 1;
}

// ============================================================
// Kernel 3: tensor-core projection (R15-proven MMA core) +
// cp.async double-buffered staging: chunk c+1 streams into the
// alternate buffer while chunk c computes. Dynamic SMEM (2x29696B).
// ============================================================
__global__ __launch_bounds__(256, 2) void k_proj_mma(
    const float* __restrict__ x, const float* __restrict__ neurons)
{
    extern __shared__ __align__(16) char dyn[];
    __shared__ int psh[TILE_P];
    __shared__ int tsh[TILE_P];
    __shared__ int s_nt[NEXP];
    __shared__ int s_base[NEXP + 1];

    const int tid = threadIdx.x;
    const int wid = tid >> 5;
    const int lid = tid & 31;
    const int g   = lid >> 2;
    const int t2  = (lid & 3) * 2;
    const int strip = wid * 16;

    const u32 dynb = smem_u32(dyn);

    // ldmatrix lane-address components (R15-proven)
    const int a_row = strip + (lid & 7) + ((lid >> 3) & 1) * 8;
    const int a_kh  = ((lid >> 4) & 1) * 8;
    const int b_krow = ((lid >> 3) & 1) * 8 + (lid & 7);
    const int b_nh   = ((lid >> 4) & 1) * 8;

    // staging lane geometry
    const int apr0 = tid >> 2,           ac0 = tid & 3;          // A idx = tid
    const int apr1 = (tid + 256) >> 2,   ac1 = (tid + 256) & 3;  // A idx = tid+256
    const int bd   = tid >> 3,           bu  = tid & 7;          // B

    if (tid < NEXP) s_nt[tid] = (g_cnt[tid] + TILE_P - 1) >> 7;
    __syncthreads();
    if (tid == 0) {
        int sum = 0;
        #pragma unroll
        for (int e = 0; e < NEXP; e++) { s_base[e] = sum; sum += s_nt[e]; }
        s_base[NEXP] = sum;
    }
    __syncthreads();
    const int nwork = s_base[NEXP] * NSPLIT;

    for (int w = blockIdx.x; w < nwork; w += gridDim.x) {
        const int it = w >> 2;
        const int sp = w & 3;
        int e = 0;
        while (s_base[e + 1] <= it) e++;
        const int off = (it - s_base[e]) * TILE_P;
        int cnt = g_cnt[e] - off;
        if (cnt > TILE_P) cnt = TILE_P;

        if (tid < TILE_P) {
            if (tid < cnt) {
                int p = g_list[e * CAP + off + tid];
                psh[tid] = p;
                tsh[tid] = p >> 1;
            } else {
                psh[tid] = -1;
                tsh[tid] = -1;
            }
        }
        __syncthreads();

        const size_t nboff = (size_t)e * DIM * RANK + (size_t)sp * DSPL * RANK;
        const int dbase = sp * DSPL;
        const int tk0 = tsh[apr0];
        const int tk1 = tsh[apr1];
        const u32 sz0 = (tk0 >= 0) ? 16u : 0u;
        const u32 sz1 = (tk1 >= 0) ? 16u : 0u;
        const size_t xo0b = (size_t)(tk0 >= 0 ? tk0 : 0) * DIM + dbase + 8 * ac0;
        const size_t xo1b = (size_t)(tk1 >= 0 ? tk1 : 0) * DIM + dbase + 8 * ac1;

        #define P_STAGE(ci, bufofs) do { \
            int _dc = (ci) * 32; \
            u32 _b = dynb + (bufofs); \
            cp16(_b + PB_AH + apr0 * 80 + ac0 * 16, g_xh + xo0b + _dc, sz0); \
            cp16(_b + PB_AL + apr0 * 80 + ac0 * 16, g_xl + xo0b + _dc, sz0); \
            cp16(_b + PB_AH + apr1 * 80 + ac1 * 16, g_xh + xo1b + _dc, sz1); \
            cp16(_b + PB_AL + apr1 * 80 + ac1 * 16, g_xl + xo1b + _dc, sz1); \
            size_t _no = nboff + (size_t)(_dc + bd) * RANK + 8 * bu; \
            cp16(_b + PB_BH + bd * 144 + bu * 16, g_nh + _no, 16u); \
            cp16(_b + PB_BL + bd * 144 + bu * 16, g_nl + _no, 16u); \
            cp_commit(); \
        } while (0)

        float C[8][4];
        #pragma unroll
        for (int j = 0; j < 8; j++)
            #pragma unroll
            for (int q = 0; q < 4; q++) C[j][q] = 0.0f;

        P_STAGE(0, 0);

        for (int ci = 0; ci < DSPL / 32; ci++) {
            const u32 bofs = (u32)(ci & 1) * PB_SZ;
            if (ci < DSPL / 32 - 1) {
                P_STAGE(ci + 1, ((ci + 1) & 1) * PB_SZ);
                cp_wait<1>();
            } else {
                cp_wait<0>();
            }
            __syncthreads();

            const u32 AH_b = dynb + bofs + PB_AH;
            const u32 AL_b = dynb + bofs + PB_AL;
            const u32 BH_b = dynb + bofs + PB_BH;
            const u32 BL_b = dynb + bofs + PB_BL;

            #pragma unroll
            for (int koff = 0; koff < 32; koff += 16) {
                u32 ah[4], al[4];
                {
                    u32 ao = (u32)(a_row * 40 + koff + a_kh) * 2;
                    ldsm_x4(ah[0], ah[1], ah[2], ah[3], AH_b + ao);
                    ldsm_x4(al[0], al[1], al[2], al[3], AL_b + ao);
                }
                #pragma unroll
                for (int q = 0; q < 4; q++) {
                    u32 bo = (u32)((koff + b_krow) * 72 + 16 * q + b_nh) * 2;
                    u32 bh0a, bh1a, bh0b, bh1b, bl0a, bl1a, bl0b, bl1b;
                    ldsm_x4_t(bh0a, bh1a, bh0b, bh1b, BH_b + bo);
                    ldsm_x4_t(bl0a, bl1a, bl0b, bl1b, BL_b + bo);
                    mma16816(C[2*q],   ah, bh0a, bh1a);
                    mma16816(C[2*q],   ah, bl0a, bl1a);
                    mma16816(C[2*q],   al, bh0a, bh1a);
                    mma16816(C[2*q+1], ah, bh0b, bh1b);
                    mma16816(C[2*q+1], ah, bl0b, bl1b);
                    mma16816(C[2*q+1], al, bh0b, bh1b);
                }
            }
            __syncthreads();
        }
        #undef P_STAGE

        // epilogue: C frag -> disjoint (split, pick) scratch rows
        float* sb = g_scratch + (size_t)sp * (TOKENS * 2) * RANK;
        int p0 = psh[strip + g];
        int p1 = psh[strip + g + 8];
        #pragma unroll
        for (int j = 0; j < 8; j++) {
            if (p0 >= 0)
                *(float2*)(sb + (size_t)p0 * RANK + 8*j + t2) = make_float2(C[j][0], C[j][1]);
            if (p1 >= 0)
                *(float2*)(sb + (size_t)p1 * RANK + 8*j + t2) = make_float2(C[j][2], C[j][3]);
        }
        __syncthreads();
    }
}

// ============================================================
// Kernel 4: deterministic reduce: out[t,r] = sum_k w_k * sum_s part
// ============================================================
__global__ __launch_bounds__(256) void k_reduce(float* __restrict__ out) {
    int i = blockIdx.x * blockDim.x + threadIdx.x;
    int t = i >> 4;
    int c = (i & 15) * 4;
    float4 acc = make_float4(0.f, 0.f, 0.f, 0.f);
    #pragma unroll
    for (int k = 0; k < 2; k++) {
        int p = t*2 + k;
        float w = g_w[p];
        #pragma unroll
        for (int s = 0; s < NSPLIT; s++) {
            float4 v = *(const float4*)&g_scratch[((size_t)s * (TOKENS*2) + p) * RANK + c];
            acc.x += w * v.x; acc.y += w * v.y; acc.z += w * v.z; acc.w += w * v.w;
        }
    }
    *(float4*)&out[(size_t)t * RANK + c] = acc;
}

// ============================================================
extern "C" void kernel_launch(void* const* d_in, const int* in_sizes, int n_in,
                              void* d_out, int out_size) {
    const float* x       = (const float*)d_in[0];
    const float* router  = (const float*)d_in[1];
    const float* neurons = (const float*)d_in[2];
    float* out = (float*)d_out;

    cudaFuncSetAttribute(k_proj_mma, cudaFuncAttributeMaxDynamicSharedMemorySize,
                         PROJ_DYN_SMEM);

    k_nconv<<<NEXP * DIM * RANK / 4 / 256, 256>>>(neurons);
    k_router<<<dim3(TOKENS/64, 2), 256>>>(x, router);
    k_top2<<<TOKENS/128, 128>>>(out, out_size);
    k_proj_mma<<<296, 256, PROJ_DYN_SMEM>>>(x, neurons);
    k_reduce<<<TOKENS*RANK/4/256, 256>>>(out);
}

// round 17
// speedup vs baseline: 1.3626x; 1.0700x over previous
#include <cuda_runtime.h>
#include <cuda_bf16.h>
#include <math.h>

// Problem: B=2, S=2048, D=1024, N_COMPRESS=64, RANK=64, TOP_K=2
#define TOKENS 4096
#define DIM    1024
#define NEXP   64
#define RANK   64
#define CAP    8192
#define NSPLIT 4          // proj D-splits (256 d each)
#define DSPL   256
#define TILE_P 128        // picks per proj tile (MMA M)

#define OFF_IDX (TOKENS * RANK)
#define OFF_W   (TOKENS * RANK + TOKENS*2)

typedef unsigned long long ull;
typedef unsigned int u32;
typedef unsigned short u16;

__device__ __forceinline__ ull fma2(ull a, ull b, ull c) {
    ull d; asm("fma.rn.f32x2 %0, %1, %2, %3;" : "=l"(d) : "l"(a), "l"(b), "l"(c)); return d;
}
__device__ __forceinline__ float2 unpack2(ull v) {
    float2 r; asm("mov.b64 {%0, %1}, %2;" : "=f"(r.x), "=f"(r.y) : "l"(v)); return r;
}
__device__ __forceinline__ void mma16816(float* c, const u32* a, u32 b0, u32 b1) {
    asm volatile(
        "mma.sync.aligned.m16n8k16.row.col.f32.bf16.bf16.f32 "
        "{%0,%1,%2,%3}, {%4,%5,%6,%7}, {%8,%9}, {%0,%1,%2,%3};"
        : "+f"(c[0]), "+f"(c[1]), "+f"(c[2]), "+f"(c[3])
        : "r"(a[0]), "r"(a[1]), "r"(a[2]), "r"(a[3]), "r"(b0), "r"(b1));
}
__device__ __forceinline__ void ldsm_x4(u32& r0, u32& r1, u32& r2, u32& r3, u32 addr) {
    asm volatile("ldmatrix.sync.aligned.m8n8.x4.shared.b16 {%0,%1,%2,%3}, [%4];"
        : "=r"(r0), "=r"(r1), "=r"(r2), "=r"(r3) : "r"(addr));
}
__device__ __forceinline__ void ldsm_x4_t(u32& r0, u32& r1, u32& r2, u32& r3, u32 addr) {
    asm volatile("ldmatrix.sync.aligned.m8n8.x4.trans.shared.b16 {%0,%1,%2,%3}, [%4];"
        : "=r"(r0), "=r"(r1), "=r"(r2), "=r"(r3) : "r"(addr));
}
__device__ __forceinline__ u32 smem_u32(const void* p) {
    u32 a;
    asm("{ .reg .u64 t; cvta.to.shared.u64 t, %1; cvt.u32.u64 %0, t; }" : "=r"(a) : "l"(p));
    return a;
}
__device__ __forceinline__ u32 pack_bf2(__nv_bfloat16 lo, __nv_bfloat16 hi) {
    return ((u32)__bfloat16_as_ushort(hi) << 16) | __bfloat16_as_ushort(lo);
}
__device__ __forceinline__ void cp16(u32 dst, const void* src, u32 src_size) {
    asm volatile("cp.async.cg.shared.global [%0], [%1], 16, %2;"
                 :: "r"(dst), "l"(src), "r"(src_size) : "memory");
}
__device__ __forceinline__ void cp8(u32 dst, const void* src) {
    asm volatile("cp.async.ca.shared.global [%0], [%1], 8;"
                 :: "r"(dst), "l"(src) : "memory");
}
__device__ __forceinline__ void cp_commit() {
    asm volatile("cp.async.commit_group;" ::: "memory");
}
template <int N>
__device__ __forceinline__ void cp_wait() {
    asm volatile("cp.async.wait_group %0;" :: "n"(N) : "memory");
}

// dynamic smem layout for k_proj_mma (bytes, per buffer)
#define PB_AH 0
#define PB_AL 10240
#define PB_BH 20480
#define PB_BL 25088
#define PB_SZ 29696
#define PROJ_DYN_SMEM (2 * PB_SZ)

// ---- scratch (device globals) ----
__device__ int   g_cnt[NEXP];
__device__ int   g_list[NEXP * CAP];
__device__ float g_w[TOKENS * 2];
__device__ float g_part[2 * TOKENS * NEXP];
__device__ float g_scratch[NSPLIT * TOKENS * 2 * RANK];
__device__ __nv_bfloat16 g_xh[TOKENS * DIM];
__device__ __nv_bfloat16 g_xl[TOKENS * DIM];
__device__ __nv_bfloat16 g_nh[NEXP * DIM * RANK];
__device__ __nv_bfloat16 g_nl[NEXP * DIM * RANK];

// ============================================================
// Kernel 0: neurons fp32 -> bf16 hi/lo (streaming, coalesced)
// ============================================================
__global__ __launch_bounds__(256) void k_nconv(const float* __restrict__ neurons) {
    int i = (blockIdx.x * 256 + threadIdx.x) * 4;
    float4 v = *(const float4*)(neurons + i);
    __nv_bfloat16 hx = __float2bfloat16_rn(v.x);
    __nv_bfloat16 hy = __float2bfloat16_rn(v.y);
    __nv_bfloat16 hz = __float2bfloat16_rn(v.z);
    __nv_bfloat16 hw = __float2bfloat16_rn(v.w);
    __nv_bfloat16 lx = __float2bfloat16_rn(v.x - __bfloat162float(hx));
    __nv_bfloat16 ly = __float2bfloat16_rn(v.y - __bfloat162float(hy));
    __nv_bfloat16 lz = __float2bfloat16_rn(v.z - __bfloat162float(hz));
    __nv_bfloat16 lw = __float2bfloat16_rn(v.w - __bfloat162float(hw));
    *(uint2*)(g_nh + i) = make_uint2(pack_bf2(hx, hy), pack_bf2(hz, hw));
    *(uint2*)(g_nl + i) = make_uint2(pack_bf2(lx, ly), pack_bf2(lz, lw));
}

// ============================================================
// Kernel 1: router partials, cp.async double-buffered (R16-proven
// pipeline pattern). 64 tokens x 64 experts per block over 512 d,
// grid (64, 2). FMA loop identical to the R8 baseline.
// x staged via cp16 (xs stride 36: 144B rows, 16B-aligned);
// W staged via cp8  (ws stride 34: 136B rows, 8B-aligned, keeps
// the proven conflict-free b-operand banks).
// x -> bf16 hi/lo conversion reads the staged SMEM during compute.
// ============================================================
__global__ __launch_bounds__(256) void k_router(
    const float* __restrict__ x, const float* __restrict__ W)
{
    __shared__ __align__(16) float xs[2][64][36];
    __shared__ __align__(16) float ws[2][64][34];

    const int tid = threadIdx.x;
    if (blockIdx.x == 0 && blockIdx.y == 0 && tid < NEXP) g_cnt[tid] = 0;

    const int ty  = tid >> 4;
    const int tx  = tid & 15;
    const int tok0 = blockIdx.x * 64;
    const int d0   = blockIdx.y * 512;

    const u32 xs_b = smem_u32(&xs[0][0][0]);
    const u32 ws_b = smem_u32(&ws[0][0][0]);
    const u32 XBUF = 64 * 36 * 4;
    const u32 WBUF = 64 * 34 * 4;

    // staging lane geometry
    const int lt0 = tid >> 3,         lc0 = tid & 7;          // x slot 0
    const int lt1 = (tid + 256) >> 3, lc1 = (tid + 256) & 7;  // x slot 1

    #define R_STAGE(dc, buf) do { \
        cp16(xs_b + (buf) * XBUF + lt0 * 144 + lc0 * 16, \
             x + (size_t)(tok0 + lt0) * DIM + d0 + (dc) + 4 * lc0, 16u); \
        cp16(xs_b + (buf) * XBUF + lt1 * 144 + lc1 * 16, \
             x + (size_t)(tok0 + lt1) * DIM + d0 + (dc) + 4 * lc1, 16u); \
        _Pragma("unroll") \
        for (int _s = 0; _s < 4; _s++) { \
            int _idx = tid + 256 * _s;          /* 0..1023 */ \
            int _t = _idx >> 4, _u = _idx & 15; /* row, 8B unit */ \
            cp8(ws_b + (buf) * WBUF + _t * 136 + _u * 8, \
                W + (size_t)_t * DIM + d0 + (dc) + 2 * _u); \
        } \
        cp_commit(); \
    } while (0)

    ull acc[4][4];
    #pragma unroll
    for (int i = 0; i < 4; i++)
        #pragma unroll
        for (int j = 0; j < 4; j++) acc[i][j] = 0ull;

    R_STAGE(0, 0);

    for (int ci = 0; ci < 16; ci++) {
        const int cur = ci & 1;
        if (ci < 15) {
            R_STAGE((ci + 1) * 32, cur ^ 1);
            cp_wait<1>();
        } else {
            cp_wait<0>();
        }
        __syncthreads();

        // x -> bf16 hi/lo conversion from the staged SMEM (this thread's slots)
        {
            const int dc = ci * 32;
            #pragma unroll
            for (int s = 0; s < 2; s++) {
                int lt = s ? lt1 : lt0;
                int lc = s ? lc1 : lc0;
                float4 v = *(const float4*)&xs[cur][lt][4 * lc];
                __nv_bfloat16 hx = __float2bfloat16_rn(v.x);
                __nv_bfloat16 hy = __float2bfloat16_rn(v.y);
                __nv_bfloat16 hz = __float2bfloat16_rn(v.z);
                __nv_bfloat16 hw = __float2bfloat16_rn(v.w);
                __nv_bfloat16 lx = __float2bfloat16_rn(v.x - __bfloat162float(hx));
                __nv_bfloat16 ly = __float2bfloat16_rn(v.y - __bfloat162float(hy));
                __nv_bfloat16 lz = __float2bfloat16_rn(v.z - __bfloat162float(hz));
                __nv_bfloat16 lw = __float2bfloat16_rn(v.w - __bfloat162float(hw));
                size_t xoff = (size_t)(tok0 + lt) * DIM + d0 + dc + 4 * lc;
                *(uint2*)(g_xh + xoff) = make_uint2(pack_bf2(hx, hy), pack_bf2(hz, hw));
                *(uint2*)(g_xl + xoff) = make_uint2(pack_bf2(lx, ly), pack_bf2(lz, lw));
            }
        }

        #pragma unroll
        for (int k = 0; k < 32; k += 4) {
            ulonglong2 a[4];
            #pragma unroll
            for (int i = 0; i < 4; i++)
                a[i] = *(const ulonglong2*)&xs[cur][ty + 16*i][k];
            #pragma unroll
            for (int h = 0; h < 2; h++) {
                ull b[4];
                #pragma unroll
                for (int j = 0; j < 4; j++) b[j] = *(const ull*)&ws[cur][tx + 16*j][k + 2*h];
                #pragma unroll
                for (int i = 0; i < 4; i++) {
                    ull av = h ? a[i].y : a[i].x;
                    #pragma unroll
                    for (int j = 0; j < 4; j++)
                        acc[i][j] = fma2(av, b[j], acc[i][j]);
                }
            }
        }
        __syncthreads();
    }
    #undef R_STAGE

    float* dst = g_part + (size_t)blockIdx.y * TOKENS * NEXP + (size_t)tok0 * NEXP;
    #pragma unroll
    for (int i = 0; i < 4; i++)
        #pragma unroll
        for (int j = 0; j < 4; j++) {
            float2 p = unpack2(acc[i][j]);
            dst[(ty + 16*i) * NEXP + tx + 16*j] = p.x + p.y;
        }
}

// ============================================================
// Kernel 2: combine 2 partials, top-2, softmax, outputs, scatter.
// ============================================================
__global__ __launch_bounds__(128) void k_top2(float* __restrict__ out, int out_size) {
    int t = blockIdx.x * blockDim.x + threadIdx.x;
    const float4* p0 = (const float4*)(g_part) + (size_t)t * 16;
    const float4* p1 = (const float4*)(g_part + (size_t)TOKENS * NEXP) + (size_t)t * 16;

    float m0 = -1e30f, m1 = -1e30f; int i0 = 0, i1 = 0;
    #pragma unroll
    for (int c = 0; c < 16; c++) {
        float4 a = p0[c], b = p1[c];
        float s[4] = { a.x + b.x, a.y + b.y, a.z + b.z, a.w + b.w };
        #pragma unroll
        for (int e = 0; e < 4; e++) {
            int n = 4*c + e;
            float v = s[e];
            if (v > m0)      { m1 = m0; i1 = i0; m0 = v; i0 = n; }
            else if (v > m1) { m1 = v; i1 = n; }
        }
    }
    float w0 = 1.0f / (1.0f + __expf(m1 - m0));
    float w1 = 1.0f - w0;

    g_w[t*2 + 0] = w0;
    g_w[t*2 + 1] = w1;
    if (out_size >= OFF_IDX + TOKENS*2) {
        out[OFF_IDX + t*2 + 0] = (float)i0;
        out[OFF_IDX + t*2 + 1] = (float)i1;
    }
    if (out_size >= OFF_W + TOKENS*2) {
        out[OFF_W + t*2 + 0] = w0;
        out[OFF_W + t*2 + 1] = w1;
    }
    int p = atomicAdd(&g_cnt[i0], 1);
    g_list[i0 * CAP + p] = t*2 + 0;
    p = atomicAdd(&g_cnt[i1], 1);
    g_list[i1 * CAP + p] = t*2 + 1;
}

// ============================================================
// Kernel 3: tensor-core projection (R16-proven, byte-identical).
// ============================================================
__global__ __launch_bounds__(256, 2) void k_proj_mma(
    const float* __restrict__ x, const float* __restrict__ neurons)
{
    extern __shared__ __align__(16) char dyn[];
    __shared__ int psh[TILE_P];
    __shared__ int tsh[TILE_P];
    __shared__ int s_nt[NEXP];
    __shared__ int s_base[NEXP + 1];

    const int tid = threadIdx.x;
    const int wid = tid >> 5;
    const int lid = tid & 31;
    const int g   = lid >> 2;
    const int t2  = (lid & 3) * 2;
    const int strip = wid * 16;

    const u32 dynb = smem_u32(dyn);

    const int a_row = strip + (lid & 7) + ((lid >> 3) & 1) * 8;
    const int a_kh  = ((lid >> 4) & 1) * 8;
    const int b_krow = ((lid >> 3) & 1) * 8 + (lid & 7);
    const int b_nh   = ((lid >> 4) & 1) * 8;

    const int apr0 = tid >> 2,           ac0 = tid & 3;
    const int apr1 = (tid + 256) >> 2,   ac1 = (tid + 256) & 3;
    const int bd   = tid >> 3,           bu  = tid & 7;

    if (tid < NEXP) s_nt[tid] = (g_cnt[tid] + TILE_P - 1) >> 7;
    __syncthreads();
    if (tid == 0) {
        int sum = 0;
        #pragma unroll
        for (int e = 0; e < NEXP; e++) { s_base[e] = sum; sum += s_nt[e]; }
        s_base[NEXP] = sum;
    }
    __syncthreads();
    const int nwork = s_base[NEXP] * NSPLIT;

    for (int w = blockIdx.x; w < nwork; w += gridDim.x) {
        const int it = w >> 2;
        const int sp = w & 3;
        int e = 0;
        while (s_base[e + 1] <= it) e++;
        const int off = (it - s_base[e]) * TILE_P;
        int cnt = g_cnt[e] - off;
        if (cnt > TILE_P) cnt = TILE_P;

        if (tid < TILE_P) {
            if (tid < cnt) {
                int p = g_list[e * CAP + off + tid];
                psh[tid] = p;
                tsh[tid] = p >> 1;
            } else {
                psh[tid] = -1;
                tsh[tid] = -1;
            }
        }
        __syncthreads();

        const size_t nboff = (size_t)e * DIM * RANK + (size_t)sp * DSPL * RANK;
        const int dbase = sp * DSPL;
        const int tk0 = tsh[apr0];
        const int tk1 = tsh[apr1];
        const u32 sz0 = (tk0 >= 0) ? 16u : 0u;
        const u32 sz1 = (tk1 >= 0) ? 16u : 0u;
        const size_t xo0b = (size_t)(tk0 >= 0 ? tk0 : 0) * DIM + dbase + 8 * ac0;
        const size_t xo1b = (size_t)(tk1 >= 0 ? tk1 : 0) * DIM + dbase + 8 * ac1;

        #define P_STAGE(ci, bufofs) do { \
            int _dc = (ci) * 32; \
            u32 _b = dynb + (bufofs); \
            cp16(_b + PB_AH + apr0 * 80 + ac0 * 16, g_xh + xo0b + _dc, sz0); \
            cp16(_b + PB_AL + apr0 * 80 + ac0 * 16, g_xl + xo0b + _dc, sz0); \
            cp16(_b + PB_AH + apr1 * 80 + ac1 * 16, g_xh + xo1b + _dc, sz1); \
            cp16(_b + PB_AL + apr1 * 80 + ac1 * 16, g_xl + xo1b + _dc, sz1); \
            size_t _no = nboff + (size_t)(_dc + bd) * RANK + 8 * bu; \
            cp16(_b + PB_BH + bd * 144 + bu * 16, g_nh + _no, 16u); \
            cp16(_b + PB_BL + bd * 144 + bu * 16, g_nl + _no, 16u); \
            cp_commit(); \
        } while (0)

        float C[8][4];
        #pragma unroll
        for (int j = 0; j < 8; j++)
            #pragma unroll
            for (int q = 0; q < 4; q++) C[j][q] = 0.0f;

        P_STAGE(0, 0);

        for (int ci = 0; ci < DSPL / 32; ci++) {
            const u32 bofs = (u32)(ci & 1) * PB_SZ;
            if (ci < DSPL / 32 - 1) {
                P_STAGE(ci + 1, ((ci + 1) & 1) * PB_SZ);
                cp_wait<1>();
            } else {
                cp_wait<0>();
            }
            __syncthreads();

            const u32 AH_b = dynb + bofs + PB_AH;
            const u32 AL_b = dynb + bofs + PB_AL;
            const u32 BH_b = dynb + bofs + PB_BH;
            const u32 BL_b = dynb + bofs + PB_BL;

            #pragma unroll
            for (int koff = 0; koff < 32; koff += 16) {
                u32 ah[4], al[4];
                {
                    u32 ao = (u32)(a_row * 40 + koff + a_kh) * 2;
                    ldsm_x4(ah[0], ah[1], ah[2], ah[3], AH_b + ao);
                    ldsm_x4(al[0], al[1], al[2], al[3], AL_b + ao);
                }
                #pragma unroll
                for (int q = 0; q < 4; q++) {
                    u32 bo = (u32)((koff + b_krow) * 72 + 16 * q + b_nh) * 2;
                    u32 bh0a, bh1a, bh0b, bh1b, bl0a, bl1a, bl0b, bl1b;
                    ldsm_x4_t(bh0a, bh1a, bh0b, bh1b, BH_b + bo);
                    ldsm_x4_t(bl0a, bl1a, bl0b, bl1b, BL_b + bo);
                    mma16816(C[2*q],   ah, bh0a, bh1a);
                    mma16816(C[2*q],   ah, bl0a, bl1a);
                    mma16816(C[2*q],   al, bh0a, bh1a);
                    mma16816(C[2*q+1], ah, bh0b, bh1b);
                    mma16816(C[2*q+1], ah, bl0b, bl1b);
                    mma16816(C[2*q+1], al, bh0b, bh1b);
                }
            }
            __syncthreads();
        }
        #undef P_STAGE

        float* sb = g_scratch + (size_t)sp * (TOKENS * 2) * RANK;
        int p0 = psh[strip + g];
        int p1 = psh[strip + g + 8];
        #pragma unroll
        for (int j = 0; j < 8; j++) {
            if (p0 >= 0)
                *(float2*)(sb + (size_t)p0 * RANK + 8*j + t2) = make_float2(C[j][0], C[j][1]);
            if (p1 >= 0)
                *(float2*)(sb + (size_t)p1 * RANK + 8*j + t2) = make_float2(C[j][2], C[j][3]);
        }
        __syncthreads();
    }
}

// ============================================================
// Kernel 4: deterministic reduce: out[t,r] = sum_k w_k * sum_s part
// ============================================================
__global__ __launch_bounds__(256) void k_reduce(float* __restrict__ out) {
    int i = blockIdx.x * blockDim.x + threadIdx.x;
    int t = i >> 4;
    int c = (i & 15) * 4;
    float4 acc = make_float4(0.f, 0.f, 0.f, 0.f);
    #pragma unroll
    for (int k = 0; k < 2; k++) {
        int p = t*2 + k;
        float w = g_w[p];
        #pragma unroll
        for (int s = 0; s < NSPLIT; s++) {
            float4 v = *(const float4*)&g_scratch[((size_t)s * (TOKENS*2) + p) * RANK + c];
            acc.x += w * v.x; acc.y += w * v.y; acc.z += w * v.z; acc.w += w * v.w;
        }
    }
    *(float4*)&out[(size_t)t * RANK + c] = acc;
}

// ============================================================
extern "C" void kernel_launch(void* const* d_in, const int* in_sizes, int n_in,
                              void* d_out, int out_size) {
    const float* x       = (const float*)d_in[0];
    const float* router  = (const float*)d_in[1];
    const float* neurons = (const float*)d_in[2];
    float* out = (float*)d_out;

    cudaFuncSetAttribute(k_proj_mma, cudaFuncAttributeMaxDynamicSharedMemorySize,
                         PROJ_DYN_SMEM);

    k_nconv<<<NEXP * DIM * RANK / 4 / 256, 256>>>(neurons);
    k_router<<<dim3(TOKENS/64, 2), 256>>>(x, router);
    k_top2<<<TOKENS/128, 128>>>(out, out_size);
    k_proj_mma<<<296, 256, PROJ_DYN_SMEM>>>(x, neurons);
    k_reduce<<<TOKENS*RANK/4/256, 256>>>(out);
}